// round 5
// baseline (speedup 1.0000x reference)
#include <cuda_runtime.h>

// VoxelMorph SpatialTransformer, trilinear, zero padding, direct gather.
// R1 warp mapping (32 x-contiguous voxels per warp: minimal distinct-row
// footprint), int32 indexing, and aligned-float2 corner-pair loads.
// src:  [B=2, C=2, 160, 192, 160] f32
// flow: [B=2, 3,   160, 192, 160] f32  (dz, dy, dx)
// out:  [B=2, C=2, 160, 192, 160] f32

namespace {
constexpr int D = 160, H = 192, W = 160, C = 2, B = 2;
constexpr int N  = D * H * W;       // 4,915,200 (all offsets fit int32)
constexpr int HW = H * W;
}

// Linear interp along x on one corner row: gx*row[x0] + fx*row[x0+1].
// Row base is 8B-aligned (W even), so the float2 at (x0 & ~1) is aligned.
// Precondition: 0 <= x0 <= W-2.
__device__ __forceinline__ float lerp_row(const float* __restrict__ row,
                                          int x0, float fx, float gx)
{
    const float2 p = __ldg((const float2*)(row + (x0 & ~1)));
    float va, vb;
    if (x0 & 1) {                       // odd: pair is (p.y, row[x0+1])
        va = p.y;
        vb = __ldg(row + x0 + 1);       // predicated load, ~50% of lanes
    } else {                            // even: pair fully inside p
        va = p.x;
        vb = p.y;
    }
    return gx * va + fx * vb;
}

__global__ __launch_bounds__(256)
void st_warp_kernel(const float* __restrict__ src,
                    const float* __restrict__ flow,
                    float* __restrict__ out)
{
    const int s = blockIdx.x * 256 + threadIdx.x;
    if (s >= N) return;
    const int b = blockIdx.y;

    const int w = s % W;
    const int t = s / W;
    const int h = t % H;
    const int d = t / H;

    const float* fb = flow + b * 3 * N;
    const float z = (float)d + __ldg(fb + s);
    const float y = (float)h + __ldg(fb + s + N);
    const float x = (float)w + __ldg(fb + s + 2 * N);

    const float z0f = floorf(z), y0f = floorf(y), x0f = floorf(x);
    const float fz = z - z0f, fy = y - y0f, fx = x - x0f;
    const int z0 = (int)z0f, y0 = (int)y0f, x0 = (int)x0f;
    const float gz = 1.0f - fz, gy = 1.0f - fy, gx = 1.0f - fx;

    const float* s0 = src + b * C * N;  // channel 0
    const float* s1 = s0 + N;           // channel 1

    float a0 = 0.0f, a1 = 0.0f;

    if (z0 >= 0 && z0 < D - 1 && y0 >= 0 && y0 < H - 1 && x0 >= 0 && x0 < W - 1) {
        // interior fast path
        const int rbase = (z0 * H + y0) * W;
        const float w00 = gz * gy, w01 = gz * fy, w10 = fz * gy, w11 = fz * fy;

        const float* r0 = s0 + rbase;
        a0 = w00 * lerp_row(r0,          x0, fx, gx)
           + w01 * lerp_row(r0 + W,      x0, fx, gx)
           + w10 * lerp_row(r0 + HW,     x0, fx, gx)
           + w11 * lerp_row(r0 + HW + W, x0, fx, gx);

        const float* r1 = s1 + rbase;
        a1 = w00 * lerp_row(r1,          x0, fx, gx)
           + w01 * lerp_row(r1 + W,      x0, fx, gx)
           + w10 * lerp_row(r1 + HW,     x0, fx, gx)
           + w11 * lerp_row(r1 + HW + W, x0, fx, gx);
    } else {
        // boundary path: per-corner validity (zero padding)
        #pragma unroll
        for (int dz = 0; dz < 2; ++dz) {
            const int zi = z0 + dz;
            if ((unsigned)zi >= (unsigned)D) continue;
            const float wz = dz ? fz : gz;
            #pragma unroll
            for (int dy = 0; dy < 2; ++dy) {
                const int yi = y0 + dy;
                if ((unsigned)yi >= (unsigned)H) continue;
                const float wzy = wz * (dy ? fy : gy);
                #pragma unroll
                for (int dx = 0; dx < 2; ++dx) {
                    const int xi = x0 + dx;
                    if ((unsigned)xi >= (unsigned)W) continue;
                    const float wgt = wzy * (dx ? fx : gx);
                    const int lin = (zi * H + yi) * W + xi;
                    a0 += wgt * __ldg(s0 + lin);
                    a1 += wgt * __ldg(s1 + lin);
                }
            }
        }
    }

    float* ob = out + b * C * N;
    ob[s]     = a0;
    ob[s + N] = a1;
}

extern "C" void kernel_launch(void* const* d_in, const int* in_sizes, int n_in,
                              void* d_out, int out_size)
{
    const float* src  = (const float*)d_in[0];
    const float* flow = (const float*)d_in[1];
    float* out = (float*)d_out;

    dim3 block(256);
    dim3 grid((N + 255) / 256, B, 1);
    st_warp_kernel<<<grid, block>>>(src, flow, out);
}

// round 6
// speedup vs baseline: 1.4277x; 1.4277x over previous
#include <cuda_runtime.h>

// VoxelMorph SpatialTransformer, trilinear, zero padding.
// Smem-tiled gather, v2: int32 indexing, channel-interleaved float2 smem,
// warp-per-row coalesced fill, reference-exact global-coordinate rounding.
// src:  [B=2, C=2, 160, 192, 160] f32
// flow: [B=2, 3,   160, 192, 160] f32  (dz, dy, dx)
// out:  [B=2, C=2, 160, 192, 160] f32

namespace {
constexpr int D = 160, H = 192, W = 160, C = 2, B = 2;
constexpr int N  = D * H * W;           // fits int32 (B*C*N < 2^31)

constexpr int TZ = 8, TY = 16, TX = 32; // output tile per block
constexpr int R  = 3;                   // halo radius
constexpr int SZ = TZ + 1 + 2 * R;      // 15
constexpr int SY = TY + 1 + 2 * R;      // 23
constexpr int SXV = TX + 1 + 2 * R;     // 39 valid x entries
constexpr int SXP = 40;                 // padded x stride (float2 units)
constexpr int PAIRS = SZ * SY * SXP;    // 13800 float2
constexpr int SMEM_BYTES = PAIRS * 8;   // 110400
constexpr int NZT = D / TZ;             // 20
}

__global__ __launch_bounds__(512, 2)
void st_smem2_kernel(const float* __restrict__ src,
                     const float* __restrict__ flow,
                     float* __restrict__ out)
{
    extern __shared__ float2 sm2[];     // [SZ][SY][SXP], .x=ch0 .y=ch1

    const int bzz = blockIdx.z;
    const int b   = bzz / NZT;
    const int z_t = (bzz - b * NZT) * TZ;
    const int y_t = blockIdx.y * TY;
    const int x_t = blockIdx.x * TX;
    const int z_lo = z_t - R, y_lo = y_t - R, x_lo = x_t - R;

    const int tid  = threadIdx.y * TX + threadIdx.x;
    const int lane = tid & 31;
    const int warp = tid >> 5;          // 0..15

    const float* s0 = src + b * C * N;  // channel 0 base
    const float* s1 = s0 + N;

    // ---- fill: one warp per (z,y) row, both channels, coalesced ----
    for (int r = warp; r < SZ * SY; r += 16) {
        const int sz = r / SY;
        const int sy = r - sz * SY;
        const int gz = z_lo + sz;
        const int gy = y_lo + sy;
        const bool rv = ((unsigned)gz < (unsigned)D) & ((unsigned)gy < (unsigned)H);
        const int roff = (gz * H + gy) * W + x_lo;
        float2* dst = sm2 + (sz * SY + sy) * SXP;

        {
            const int sx = lane;                    // 0..31
            const int gx = x_lo + sx;
            const bool v = rv & ((unsigned)gx < (unsigned)W);
            float a = 0.f, c = 0.f;
            if (v) { a = __ldg(s0 + roff + sx); c = __ldg(s1 + roff + sx); }
            dst[sx] = make_float2(a, c);
        }
        if (lane < SXV - 32) {                      // 7 tail elements
            const int sx = lane + 32;
            const int gx = x_lo + sx;
            const bool v = rv & ((unsigned)gx < (unsigned)W);
            float a = 0.f, c = 0.f;
            if (v) { a = __ldg(s0 + roff + sx); c = __ldg(s1 + roff + sx); }
            dst[sx] = make_float2(a, c);
        }
    }
    __syncthreads();

    // ---- gather ----
    const int ty = threadIdx.y;
    const int tx = threadIdx.x;
    const int h  = y_t + ty;
    const int w  = x_t + tx;

    const float* fb = flow + b * 3 * N;
    float* ob = out + b * C * N;

    #pragma unroll
    for (int z = 0; z < TZ; ++z) {
        const int d = z_t + z;
        const int s = (d * H + h) * W + w;

        // global coords — matches reference rounding exactly
        const float zf = (float)d + __ldg(fb + s);
        const float yf = (float)h + __ldg(fb + s + N);
        const float xf = (float)w + __ldg(fb + s + 2 * N);

        const float z0f = floorf(zf), y0f = floorf(yf), x0f = floorf(xf);
        const float fz = zf - z0f, fy = yf - y0f, fx = xf - x0f;
        const int z0 = (int)z0f, y0 = (int)y0f, x0 = (int)x0f;
        const float gz = 1.0f - fz, gy = 1.0f - fy, gx = 1.0f - fx;

        const float w00 = gz * gy, w01 = gz * fy, w10 = fz * gy, w11 = fz * fy;
        const float w000 = w00 * gx, w001 = w00 * fx;
        const float w010 = w01 * gx, w011 = w01 * fx;
        const float w100 = w10 * gx, w101 = w10 * fx;
        const float w110 = w11 * gx, w111 = w11 * fx;

        const int z0l = z0 - z_lo;
        const int y0l = y0 - y_lo;
        const int x0l = x0 - x_lo;

        float a0, a1;

        if ((unsigned)z0l <= (unsigned)(SZ - 2) &&
            (unsigned)y0l <= (unsigned)(SY - 2) &&
            (unsigned)x0l <= (unsigned)(SXV - 2)) {
            const int base = (z0l * SY + y0l) * SXP + x0l;
            const float2 c000 = sm2[base];
            const float2 c001 = sm2[base + 1];
            const float2 c010 = sm2[base + SXP];
            const float2 c011 = sm2[base + SXP + 1];
            const float2 c100 = sm2[base + SY * SXP];
            const float2 c101 = sm2[base + SY * SXP + 1];
            const float2 c110 = sm2[base + SY * SXP + SXP];
            const float2 c111 = sm2[base + SY * SXP + SXP + 1];
            a0 = w000 * c000.x + w001 * c001.x
               + w010 * c010.x + w011 * c011.x
               + w100 * c100.x + w101 * c101.x
               + w110 * c110.x + w111 * c111.x;
            a1 = w000 * c000.y + w001 * c001.y
               + w010 * c010.y + w011 * c011.y
               + w100 * c100.y + w101 * c101.y
               + w110 * c110.y + w111 * c111.y;
        } else {
            // rare fallback: sample escapes tile (|flow| > R)
            a0 = 0.0f; a1 = 0.0f;
            #pragma unroll
            for (int dz = 0; dz < 2; ++dz) {
                const int zi = z0 + dz;
                if ((unsigned)zi >= (unsigned)D) continue;
                const float wz = dz ? fz : gz;
                #pragma unroll
                for (int dy = 0; dy < 2; ++dy) {
                    const int yi = y0 + dy;
                    if ((unsigned)yi >= (unsigned)H) continue;
                    const float wzy = wz * (dy ? fy : gy);
                    #pragma unroll
                    for (int dx = 0; dx < 2; ++dx) {
                        const int xi = x0 + dx;
                        if ((unsigned)xi >= (unsigned)W) continue;
                        const float wgt = wzy * (dx ? fx : gx);
                        const int lin = (zi * H + yi) * W + xi;
                        a0 += wgt * __ldg(s0 + lin);
                        a1 += wgt * __ldg(s1 + lin);
                    }
                }
            }
        }

        ob[s]     = a0;
        ob[s + N] = a1;
    }
}

extern "C" void kernel_launch(void* const* d_in, const int* in_sizes, int n_in,
                              void* d_out, int out_size)
{
    const float* src  = (const float*)d_in[0];
    const float* flow = (const float*)d_in[1];
    float* out = (float*)d_out;

    static bool attr_done = false;
    if (!attr_done) {
        cudaFuncSetAttribute(st_smem2_kernel,
                             cudaFuncAttributeMaxDynamicSharedMemorySize,
                             SMEM_BYTES);
        attr_done = true;
    }

    dim3 block(TX, TY, 1);                  // 512 threads
    dim3 grid(W / TX, H / TY, B * NZT);     // 5, 12, 40
    st_smem2_kernel<<<grid, block, SMEM_BYTES>>>(src, flow, out);
}

// round 7
// speedup vs baseline: 1.6219x; 1.1360x over previous
#include <cuda_runtime.h>

// VoxelMorph SpatialTransformer, trilinear, zero padding.
// Smem-tiled gather v3: 8x8x32 tile (72KB smem) => 3 CTAs/SM = 48 warps,
// int32 indexing, channel-interleaved float2 smem, reference-exact rounding.
// src:  [B=2, C=2, 160, 192, 160] f32
// flow: [B=2, 3,   160, 192, 160] f32  (dz, dy, dx)
// out:  [B=2, C=2, 160, 192, 160] f32

namespace {
constexpr int D = 160, H = 192, W = 160, C = 2, B = 2;
constexpr int N  = D * H * W;

constexpr int TZ = 8, TY = 8, TX = 32;  // output tile per block
constexpr int R  = 3;
constexpr int SZ = TZ + 1 + 2 * R;      // 15
constexpr int SY = TY + 1 + 2 * R;      // 15
constexpr int SXV = TX + 1 + 2 * R;     // 39 valid x entries
constexpr int SXP = 40;                 // padded x stride (float2)
constexpr int SMEM_BYTES = SZ * SY * SXP * 8;   // 72000
constexpr int NZT = D / TZ;             // 20
constexpr int ZPT = 4;                  // z-planes per thread (2 thread z-groups)
}

__global__ __launch_bounds__(512, 3)
void st_smem3_kernel(const float* __restrict__ src,
                     const float* __restrict__ flow,
                     float* __restrict__ out)
{
    extern __shared__ float2 sm2[];     // [SZ][SY][SXP], .x=ch0 .y=ch1

    const int bzz = blockIdx.z;
    const int b   = bzz / NZT;
    const int z_t = (bzz - b * NZT) * TZ;
    const int y_t = blockIdx.y * TY;
    const int x_t = blockIdx.x * TX;
    const int z_lo = z_t - R, y_lo = y_t - R, x_lo = x_t - R;

    const int tid  = (threadIdx.z * TY + threadIdx.y) * TX + threadIdx.x;
    const int lane = tid & 31;
    const int warp = tid >> 5;          // 0..15

    const float* s0 = src + b * C * N;
    const float* s1 = s0 + N;

    // ---- fill: one warp per (z,y) row, both channels, coalesced ----
    for (int r = warp; r < SZ * SY; r += 16) {
        const int sz = r / SY;
        const int sy = r - sz * SY;
        const int gz = z_lo + sz;
        const int gy = y_lo + sy;
        const bool rv = ((unsigned)gz < (unsigned)D) & ((unsigned)gy < (unsigned)H);
        const int roff = (gz * H + gy) * W + x_lo;
        float2* dst = sm2 + r * SXP;

        {
            const int sx = lane;
            const int gx = x_lo + sx;
            const bool v = rv & ((unsigned)gx < (unsigned)W);
            float a = 0.f, c = 0.f;
            if (v) { a = __ldg(s0 + roff + sx); c = __ldg(s1 + roff + sx); }
            dst[sx] = make_float2(a, c);
        }
        if (lane < SXV - 32) {          // 7 tail elements
            const int sx = lane + 32;
            const int gx = x_lo + sx;
            const bool v = rv & ((unsigned)gx < (unsigned)W);
            float a = 0.f, c = 0.f;
            if (v) { a = __ldg(s0 + roff + sx); c = __ldg(s1 + roff + sx); }
            dst[sx] = make_float2(a, c);
        }
    }
    __syncthreads();

    // ---- gather: each thread handles ZPT z-planes ----
    const int h  = y_t + threadIdx.y;
    const int w  = x_t + threadIdx.x;
    const int z_base = z_t + threadIdx.z * ZPT;

    const float* fb = flow + b * 3 * N;
    float* ob = out + b * C * N;

    #pragma unroll
    for (int k = 0; k < ZPT; ++k) {
        const int d = z_base + k;
        const int s = (d * H + h) * W + w;

        // global coords — matches reference rounding exactly
        const float zf = (float)d + __ldg(fb + s);
        const float yf = (float)h + __ldg(fb + s + N);
        const float xf = (float)w + __ldg(fb + s + 2 * N);

        const float z0f = floorf(zf), y0f = floorf(yf), x0f = floorf(xf);
        const float fz = zf - z0f, fy = yf - y0f, fx = xf - x0f;
        const int z0 = (int)z0f, y0 = (int)y0f, x0 = (int)x0f;
        const float gz = 1.0f - fz, gy = 1.0f - fy, gx = 1.0f - fx;

        const float w00 = gz * gy, w01 = gz * fy, w10 = fz * gy, w11 = fz * fy;
        const float w000 = w00 * gx, w001 = w00 * fx;
        const float w010 = w01 * gx, w011 = w01 * fx;
        const float w100 = w10 * gx, w101 = w10 * fx;
        const float w110 = w11 * gx, w111 = w11 * fx;

        const int z0l = z0 - z_lo;
        const int y0l = y0 - y_lo;
        const int x0l = x0 - x_lo;

        float a0, a1;

        if ((unsigned)z0l <= (unsigned)(SZ - 2) &&
            (unsigned)y0l <= (unsigned)(SY - 2) &&
            (unsigned)x0l <= (unsigned)(SXV - 2)) {
            const float2* p = sm2 + (z0l * SY + y0l) * SXP + x0l;
            const float2 c000 = p[0];
            const float2 c001 = p[1];
            const float2 c010 = p[SXP];
            const float2 c011 = p[SXP + 1];
            const float2 c100 = p[SY * SXP];
            const float2 c101 = p[SY * SXP + 1];
            const float2 c110 = p[SY * SXP + SXP];
            const float2 c111 = p[SY * SXP + SXP + 1];
            a0 = w000 * c000.x + w001 * c001.x
               + w010 * c010.x + w011 * c011.x
               + w100 * c100.x + w101 * c101.x
               + w110 * c110.x + w111 * c111.x;
            a1 = w000 * c000.y + w001 * c001.y
               + w010 * c010.y + w011 * c011.y
               + w100 * c100.y + w101 * c101.y
               + w110 * c110.y + w111 * c111.y;
        } else {
            // rare fallback: sample escapes tile (|flow| > R)
            a0 = 0.0f; a1 = 0.0f;
            #pragma unroll
            for (int dz = 0; dz < 2; ++dz) {
                const int zi = z0 + dz;
                if ((unsigned)zi >= (unsigned)D) continue;
                const float wz = dz ? fz : gz;
                #pragma unroll
                for (int dy = 0; dy < 2; ++dy) {
                    const int yi = y0 + dy;
                    if ((unsigned)yi >= (unsigned)H) continue;
                    const float wzy = wz * (dy ? fy : gy);
                    #pragma unroll
                    for (int dx = 0; dx < 2; ++dx) {
                        const int xi = x0 + dx;
                        if ((unsigned)xi >= (unsigned)W) continue;
                        const float wgt = wzy * (dx ? fx : gx);
                        const int lin = (zi * H + yi) * W + xi;
                        a0 += wgt * __ldg(s0 + lin);
                        a1 += wgt * __ldg(s1 + lin);
                    }
                }
            }
        }

        ob[s]     = a0;
        ob[s + N] = a1;
    }
}

extern "C" void kernel_launch(void* const* d_in, const int* in_sizes, int n_in,
                              void* d_out, int out_size)
{
    const float* src  = (const float*)d_in[0];
    const float* flow = (const float*)d_in[1];
    float* out = (float*)d_out;

    static bool attr_done = false;
    if (!attr_done) {
        cudaFuncSetAttribute(st_smem3_kernel,
                             cudaFuncAttributeMaxDynamicSharedMemorySize,
                             SMEM_BYTES);
        attr_done = true;
    }

    dim3 block(TX, TY, 2);                  // 512 threads
    dim3 grid(W / TX, H / TY, B * NZT);     // 5, 24, 40
    st_smem3_kernel<<<grid, block, SMEM_BYTES>>>(src, flow, out);
}

// round 9
// speedup vs baseline: 2.0412x; 1.2585x over previous
#include <cuda_runtime.h>

// VoxelMorph SpatialTransformer, trilinear, zero padding.
// Smem-tiled gather v4: vectorized fill (LDG.128 + STS.128, quad-aligned via
// x-origin shift), int32 indexing, channel-interleaved float2 smem,
// reference-exact rounding. 8x8x32 tile, 72KB smem, 3 CTAs/SM.
// src:  [B=2, C=2, 160, 192, 160] f32
// flow: [B=2, 3,   160, 192, 160] f32  (dz, dy, dx)
// out:  [B=2, C=2, 160, 192, 160] f32

namespace {
constexpr int D = 160, H = 192, W = 160, C = 2, B = 2;
constexpr int N  = D * H * W;
constexpr int HW = H * W;

constexpr int TZ = 8, TY = 8, TX = 32;  // output tile
constexpr int R  = 3;
constexpr int SZ = TZ + 1 + 2 * R;      // 15 z-slices
constexpr int SY = TY + 1 + 2 * R;      // 15 y-rows
constexpr int SXP = 40;                 // x entries (float2), 16B-aligned quads
constexpr int ROWS = SZ * SY;           // 225
constexpr int QPR  = SXP / 4;           // 10 quads per row
constexpr int SMEM_BYTES = ROWS * SXP * 8;   // 72000
constexpr int NZT = D / TZ;             // 20
// smem x coordinate: x' = gx - (x_t - 4), valid gather range x' in [1, 38]
}

__global__ __launch_bounds__(512, 3)
void st_v8_kernel(const float* __restrict__ src,
                  const float* __restrict__ flow,
                  float* __restrict__ out)
{
    extern __shared__ float2 sm2[];     // [SZ*SY][SXP], .x=ch0 .y=ch1

    const int bzz = blockIdx.z;
    const int b   = bzz / NZT;
    const int z_t = (bzz - b * NZT) * TZ;
    const int y_t = blockIdx.y * TY;
    const int x_t = blockIdx.x * TX;
    const int z_lo = z_t - R, y_lo = y_t - R;
    const int x_al = x_t - 4;           // smem x' = gx - x_al

    const int tid = (threadIdx.z * TY + threadIdx.y) * TX + threadIdx.x;

    const float* s0 = src + b * C * N;
    const float* s1 = s0 + N;

    // ---- fill: (row, quad) units, all-or-nothing quad validity ----
    for (int u = tid; u < ROWS * QPR; u += 512) {
        const int row = u / QPR;
        const int qi  = u - row * QPR;
        const int sz  = row / SY;
        const int sy  = row - sz * SY;
        const int gz  = z_lo + sz;
        const int gy  = y_lo + sy;
        const int gx  = x_al + 4 * qi;  // multiple of 4; valid iff 0<=gx<W
        float4 q0 = make_float4(0.f, 0.f, 0.f, 0.f);
        float4 q1 = q0;
        if (((unsigned)gz < (unsigned)D) & ((unsigned)gy < (unsigned)H) &
            ((unsigned)gx < (unsigned)W)) {
            const int off = (gz * H + gy) * W + gx;   // 16B-aligned
            q0 = __ldg((const float4*)(s0 + off));
            q1 = __ldg((const float4*)(s1 + off));
        }
        float4* dst = (float4*)(sm2 + row * SXP + 4 * qi);  // 32B-aligned
        dst[0] = make_float4(q0.x, q1.x, q0.y, q1.y);
        dst[1] = make_float4(q0.z, q1.z, q0.w, q1.w);
    }
    __syncthreads();

    // ---- gather: each thread handles 4 z-planes ----
    const int h = y_t + threadIdx.y;
    const int w = x_t + threadIdx.x;
    const int z_b = z_t + threadIdx.z * 4;

    const float* fb = flow + b * 3 * N;
    float* ob = out + b * C * N;

    int s = (z_b * H + h) * W + w;

    #pragma unroll
    for (int k = 0; k < 4; ++k, s += HW) {
        const int d = z_b + k;

        const float zf = (float)d + __ldg(fb + s);
        const float yf = (float)h + __ldg(fb + s + N);
        const float xf = (float)w + __ldg(fb + s + 2 * N);

        const int z0 = __float2int_rd(zf);
        const int y0 = __float2int_rd(yf);
        const int x0 = __float2int_rd(xf);
        const float fz = zf - (float)z0;
        const float fy = yf - (float)y0;
        const float fx = xf - (float)x0;
        const float gz = 1.0f - fz, gy = 1.0f - fy, gx = 1.0f - fx;

        const float w00 = gz * gy, w01 = gz * fy, w10 = fz * gy, w11 = fz * fy;
        const float w000 = w00 * gx, w001 = w00 * fx;
        const float w010 = w01 * gx, w011 = w01 * fx;
        const float w100 = w10 * gx, w101 = w10 * fx;
        const float w110 = w11 * gx, w111 = w11 * fx;

        const int z0l = z0 - z_lo;      // in-tile: [0, SZ-2]
        const int y0l = y0 - y_lo;      // in-tile: [0, SY-2]
        const int x0l = x0 - x_al;      // in-tile: [1, SXP-2]

        float a0, a1;

        if (((unsigned)z0l <= (unsigned)(SZ - 2)) &
            ((unsigned)y0l <= (unsigned)(SY - 2)) &
            ((unsigned)(x0l - 1) <= (unsigned)(SXP - 3))) {
            const float2* p = sm2 + (z0l * SY + y0l) * SXP + x0l;
            const float2 c000 = p[0];
            const float2 c001 = p[1];
            const float2 c010 = p[SXP];
            const float2 c011 = p[SXP + 1];
            const float2 c100 = p[SY * SXP];
            const float2 c101 = p[SY * SXP + 1];
            const float2 c110 = p[SY * SXP + SXP];
            const float2 c111 = p[SY * SXP + SXP + 1];
            a0 = w000 * c000.x + w001 * c001.x
               + w010 * c010.x + w011 * c011.x
               + w100 * c100.x + w101 * c101.x
               + w110 * c110.x + w111 * c111.x;
            a1 = w000 * c000.y + w001 * c001.y
               + w010 * c010.y + w011 * c011.y
               + w100 * c100.y + w101 * c101.y
               + w110 * c110.y + w111 * c111.y;
        } else {
            // rare fallback: sample escapes tile (|flow| > R)
            a0 = 0.0f; a1 = 0.0f;
            #pragma unroll
            for (int dz = 0; dz < 2; ++dz) {
                const int zi = z0 + dz;
                if ((unsigned)zi >= (unsigned)D) continue;
                const float wz = dz ? fz : gz;
                #pragma unroll
                for (int dy = 0; dy < 2; ++dy) {
                    const int yi = y0 + dy;
                    if ((unsigned)yi >= (unsigned)H) continue;
                    const float wzy = wz * (dy ? fy : gy);
                    #pragma unroll
                    for (int dx = 0; dx < 2; ++dx) {
                        const int xi = x0 + dx;
                        if ((unsigned)xi >= (unsigned)W) continue;
                        const float wgt = wzy * (dx ? fx : gx);
                        const int lin = (zi * H + yi) * W + xi;
                        a0 += wgt * __ldg(s0 + lin);
                        a1 += wgt * __ldg(s1 + lin);
                    }
                }
            }
        }

        ob[s]     = a0;
        ob[s + N] = a1;
    }
}

extern "C" void kernel_launch(void* const* d_in, const int* in_sizes, int n_in,
                              void* d_out, int out_size)
{
    const float* src  = (const float*)d_in[0];
    const float* flow = (const float*)d_in[1];
    float* out = (float*)d_out;

    static bool attr_done = false;
    if (!attr_done) {
        cudaFuncSetAttribute(st_v8_kernel,
                             cudaFuncAttributeMaxDynamicSharedMemorySize,
                             SMEM_BYTES);
        attr_done = true;
    }

    dim3 block(TX, TY, 2);                  // 512 threads
    dim3 grid(W / TX, H / TY, B * NZT);     // 5, 24, 40
    st_v8_kernel<<<grid, block, SMEM_BYTES>>>(src, flow, out);
}